// round 1
// baseline (speedup 1.0000x reference)
#include <cuda_runtime.h>

#define B_   8
#define CIN  96
#define CMID 48
#define HH   256
#define WW   256
#define H2   128
#define W2   128
#define CO   192

// Scratch for conv1 output y = conv(x, w_body): (8, 48, 256, 256) fp32 = 100 MB.
__device__ float g_y[B_ * CMID * HH * WW];

// ---------------------------------------------------------------------------
// Kernel A: 3x3 conv, 96 -> 48 channels, pad 1, fp32.
// CTA tile: 16 oc x 8 rows x 32 cols. Thread tile: 4 oc x 4 cols (16 acc).
// K (input channels) chunked by 8 through shared memory.
// ---------------------------------------------------------------------------
#define OCT 16
#define ICB 8

__global__ __launch_bounds__(256) void conv1_kernel(
    const float* __restrict__ x, const float* __restrict__ w)
{
    __shared__ __align__(16) float sx[ICB][10][36];   // [ic][row(+halo)][col(+halo, padded)]
    __shared__ __align__(16) float sw[ICB][9][OCT];   // [ic][tap][oc_local]

    const int tid  = threadIdx.x;
    const int lane = tid & 31;
    const int wid  = tid >> 5;          // 0..7
    const int row  = wid;               // output row within tile
    const int colg = lane >> 2;         // 0..7
    const int ocg  = lane & 3;          // 0..3
    const int col0 = colg * 4;

    const int w0c = blockIdx.x * 32;
    const int h0  = blockIdx.y * 8;
    const int b   = blockIdx.z / 3;
    const int ocb = blockIdx.z % 3;

    float acc[4][4];
    #pragma unroll
    for (int o = 0; o < 4; o++)
        #pragma unroll
        for (int p = 0; p < 4; p++)
            acc[o][p] = 0.f;

    for (int icc = 0; icc < CIN; icc += ICB) {
        // ---- load x tile (8 ic x 10 rows x 34 cols), coalesced by row ----
        for (int rr = wid; rr < ICB * 10; rr += 8) {
            int ic = rr / 10, r = rr % 10;
            int gr = h0 - 1 + r;
            const float* xrow = x + (((b * CIN + icc + ic) * HH + gr) * WW);
            bool rowok = ((unsigned)gr < (unsigned)HH);
            int gc = w0c - 1 + lane;
            sx[ic][r][lane] = (rowok && (unsigned)gc < (unsigned)WW) ? xrow[gc] : 0.f;
            if (lane < 2) {
                int gc2 = w0c + 31 + lane;
                sx[ic][r][32 + lane] =
                    (rowok && (unsigned)gc2 < (unsigned)WW) ? xrow[gc2] : 0.f;
            }
        }
        // ---- load weight chunk: sw[ic][tap][oc_local] ----
        for (int idx = tid; idx < ICB * 9 * OCT; idx += 256) {
            int ic  = idx / (9 * OCT);
            int rem = idx % (9 * OCT);
            int tap = rem / OCT;
            int ocl = rem % OCT;
            sw[ic][tap][ocl] = w[((ocb * OCT + ocl) * CIN + icc + ic) * 9 + tap];
        }
        __syncthreads();

        #pragma unroll
        for (int ic = 0; ic < ICB; ic++) {
            #pragma unroll
            for (int kh = 0; kh < 3; kh++) {
                float4 xa = *(const float4*)&sx[ic][row + kh][col0];
                float4 xb = *(const float4*)&sx[ic][row + kh][col0 + 4];
                float xv[6] = {xa.x, xa.y, xa.z, xa.w, xb.x, xb.y};
                #pragma unroll
                for (int kw = 0; kw < 3; kw++) {
                    float4 wv = *(const float4*)&sw[ic][kh * 3 + kw][ocg * 4];
                    float wr[4] = {wv.x, wv.y, wv.z, wv.w};
                    #pragma unroll
                    for (int o = 0; o < 4; o++)
                        #pragma unroll
                        for (int p = 0; p < 4; p++)
                            acc[o][p] = fmaf(wr[o], xv[kw + p], acc[o][p]);
                }
            }
        }
        __syncthreads();
    }

    // ---- store (float4 per oc) ----
    #pragma unroll
    for (int o = 0; o < 4; o++) {
        int oc = ocb * OCT + ocg * 4 + o;
        float4 v = make_float4(acc[o][0], acc[o][1], acc[o][2], acc[o][3]);
        *(float4*)&g_y[((b * CMID + oc) * HH + (h0 + row)) * WW + w0c + col0] = v;
    }
}

// ---------------------------------------------------------------------------
// Kernel B: fused pixel_unshuffle + mask interleave + grouped 3x3 conv.
// Output channel g = 4*c + 2*dy + dx:
//   out[b,g,h,w] = sum_{kh,kw} wp[g,0,kh,kw] * y[b,c, 2(h+kh-1)+dy, 2(w+kw-1)+dx]
//                + sum_{kh,kw} wp[g,1,kh,kw] * m[b,   2(h+kh-1)+dy, 2(w+kw-1)+dx]
// One CTA handles (b, c, dy) x (8 rows x 128 cols); each thread produces
// 4 cols for BOTH dx parities (g0 = 4c+2dy, g1 = g0+1).
// SMEM tiles are de-interleaved by dx so all indexing is at 128-res with a
// 1-col zero pad on each side (column padding handled structurally).
// ---------------------------------------------------------------------------
__global__ __launch_bounds__(256) void conv2_kernel(
    const float* __restrict__ mask, const float* __restrict__ wp,
    float* __restrict__ out)
{
    __shared__ __align__(16) float sy[2][10][132];
    __shared__ __align__(16) float smm[2][10][132];
    __shared__ float swp[36];

    const int tid = threadIdx.x;
    const int hb  = blockIdx.x * 8;
    const int gp  = blockIdx.y;     // 0..95 : (c, dy)
    const int b   = blockIdx.z;
    const int c   = gp >> 1;
    const int dy  = gp & 1;
    const int g0  = 4 * c + 2 * dy;

    // weights for g0 (dx=0) and g1 (dx=1): 36 contiguous floats at wp + g0*18
    if (tid < 36) swp[tid] = wp[g0 * 18 + tid];

    // ---- load y and mask tiles, de-interleaved by dx parity ----
    for (int idx = tid; idx < 10 * 128; idx += 256) {
        int r = idx >> 7;       // 0..9 (128-res row = hb-1+r)
        int q = idx & 127;      // 128-res col
        int gy = 2 * (hb - 1 + r) + dy;
        float2 yv = make_float2(0.f, 0.f);
        float2 mv = make_float2(0.f, 0.f);
        if ((unsigned)gy < (unsigned)HH) {
            yv = *(const float2*)&g_y[(((b * CMID + c) * HH + gy) * WW) + 2 * q];
            mv = *(const float2*)&mask[((b * HH + gy) * WW) + 2 * q];
        }
        sy[0][r][1 + q] = yv.x;  sy[1][r][1 + q] = yv.y;
        smm[0][r][1 + q] = mv.x; smm[1][r][1 + q] = mv.y;
    }
    if (tid < 10) {
        sy[0][tid][0] = 0.f;   sy[1][tid][0] = 0.f;
        sy[0][tid][129] = 0.f; sy[1][tid][129] = 0.f;
        smm[0][tid][0] = 0.f;   smm[1][tid][0] = 0.f;
        smm[0][tid][129] = 0.f; smm[1][tid][129] = 0.f;
    }
    __syncthreads();

    const int hr = tid >> 5;       // 0..7
    const int wq = tid & 31;       // 0..31
    const int w0 = wq * 4;

    float a0[4] = {0.f, 0.f, 0.f, 0.f};
    float a1[4] = {0.f, 0.f, 0.f, 0.f};

    #pragma unroll
    for (int kh = 0; kh < 3; kh++) {
        int r = hr + kh;
        float4 y0a = *(const float4*)&sy[0][r][w0];
        float2 y0b = *(const float2*)&sy[0][r][w0 + 4];
        float4 y1a = *(const float4*)&sy[1][r][w0];
        float2 y1b = *(const float2*)&sy[1][r][w0 + 4];
        float4 m0a = *(const float4*)&smm[0][r][w0];
        float2 m0b = *(const float2*)&smm[0][r][w0 + 4];
        float4 m1a = *(const float4*)&smm[1][r][w0];
        float2 m1b = *(const float2*)&smm[1][r][w0 + 4];
        float yv0[6] = {y0a.x, y0a.y, y0a.z, y0a.w, y0b.x, y0b.y};
        float yv1[6] = {y1a.x, y1a.y, y1a.z, y1a.w, y1b.x, y1b.y};
        float mv0[6] = {m0a.x, m0a.y, m0a.z, m0a.w, m0b.x, m0b.y};
        float mv1[6] = {m1a.x, m1a.y, m1a.z, m1a.w, m1b.x, m1b.y};
        #pragma unroll
        for (int kw = 0; kw < 3; kw++) {
            float wy0 = swp[kh * 3 + kw];
            float wm0 = swp[9 + kh * 3 + kw];
            float wy1 = swp[18 + kh * 3 + kw];
            float wm1 = swp[27 + kh * 3 + kw];
            #pragma unroll
            for (int p = 0; p < 4; p++) {
                a0[p] = fmaf(wy0, yv0[kw + p], a0[p]);
                a0[p] = fmaf(wm0, mv0[kw + p], a0[p]);
                a1[p] = fmaf(wy1, yv1[kw + p], a1[p]);
                a1[p] = fmaf(wm1, mv1[kw + p], a1[p]);
            }
        }
    }

    const int h = hb + hr;
    *(float4*)&out[((b * CO + g0) * H2 + h) * W2 + w0] =
        make_float4(a0[0], a0[1], a0[2], a0[3]);
    *(float4*)&out[((b * CO + g0 + 1) * H2 + h) * W2 + w0] =
        make_float4(a1[0], a1[1], a1[2], a1[3]);
}

// ---------------------------------------------------------------------------
extern "C" void kernel_launch(void* const* d_in, const int* in_sizes, int n_in,
                              void* d_out, int out_size)
{
    const float* x      = (const float*)d_in[0];
    const float* mask   = (const float*)d_in[1];
    const float* w_body = (const float*)d_in[2];
    const float* w_proj = (const float*)d_in[3];
    float* out = (float*)d_out;

    dim3 gA(WW / 32, HH / 8, B_ * 3);   // (8, 32, 24)
    conv1_kernel<<<gA, 256>>>(x, w_body);

    dim3 gB(H2 / 8, 96, B_);            // (16, 96, 8)
    conv2_kernel<<<gB, 256>>>(mask, w_proj, out);
}